// round 1
// baseline (speedup 1.0000x reference)
#include <cuda_runtime.h>
#include <math.h>
#include <float.h>

#define N_      2048
#define DIM_    1024
#define H_      16
#define KVH_    8
#define GQ_     2
#define D_      64
#define WS_     64
#define CBS_    32
#define STRIDE_ 16
#define SEL_BLK_ 32
#define NSEL_   4
#define NMEM_   1
#define NCB_    128
#define NFB_    64
#define NCPF_   2
#define HID_    2048
#define SCALE_  0.125f
#define QKVW_   2048            /* (H + 2*KVH) * D */
#define CJ_     (NMEM_ + NCB_)  /* 129 */

// ---------------- scratch (static device allocations; no cudaMalloc) --------
__device__ float g_x[N_ * DIM_];
__device__ float g_qkv[N_ * QKVW_];
__device__ float g_kwflat[KVH_ * NCB_ * HID_];
__device__ float g_vwflat[KVH_ * NCB_ * HID_];
__device__ float g_h1[KVH_ * NCB_ * HID_];
__device__ float g_ckraw[KVH_ * NCB_ * D_];
__device__ float g_cvraw[KVH_ * NCB_ * D_];
__device__ float g_ck[KVH_ * CJ_ * D_];
__device__ float g_cv[KVH_ * CJ_ * D_];
__device__ float g_rq[H_ * N_ * D_];
__device__ float g_rk[KVH_ * N_ * D_];
__device__ float g_cout[H_ * N_ * D_];
__device__ float g_fout[H_ * N_ * D_];
__device__ float g_sout[H_ * N_ * D_];
__device__ float g_imp[KVH_ * N_ * NFB_];
__device__ int   g_selidx[KVH_ * N_ * 5];
__device__ int   g_selflag[KVH_ * N_ * 4];
__device__ float g_gates[N_ * H_ * 3];
__device__ float g_comb[N_ * DIM_];

// ---------------- RMSNorm ---------------------------------------------------
__global__ void rmsnorm_kernel(const float* __restrict__ inp,
                               const float* __restrict__ gamma) {
    int row = blockIdx.x;
    const float* r = inp + (size_t)row * DIM_;
    float s = 0.f;
    for (int j = threadIdx.x; j < DIM_; j += blockDim.x) { float v = r[j]; s += v * v; }
    __shared__ float sh[32];
    for (int o = 16; o; o >>= 1) s += __shfl_down_sync(0xffffffffu, s, o);
    if ((threadIdx.x & 31) == 0) sh[threadIdx.x >> 5] = s;
    __syncthreads();
    if (threadIdx.x < 32) {
        s = (threadIdx.x < (blockDim.x >> 5)) ? sh[threadIdx.x] : 0.f;
        for (int o = 16; o; o >>= 1) s += __shfl_down_sync(0xffffffffu, s, o);
        if (threadIdx.x == 0) sh[0] = rsqrtf(s / (float)DIM_ + 1.1920929e-07f);
    }
    __syncthreads();
    float rs = sh[0];
    for (int j = threadIdx.x; j < DIM_; j += blockDim.x)
        g_x[(size_t)row * DIM_ + j] = r[j] * rs * gamma[j];
}

// ---------------- SGEMM: C = act(A@B (+bias)) -------------------------------
// A (M,K) row-major, B (K,N) row-major. 64x64 tile, BK=16, 256 thr, 4x4/thr.
template <int ACT, bool BIAS>
__global__ void sgemm_kernel(const float* __restrict__ A, const float* __restrict__ B,
                             const float* __restrict__ bias, float* __restrict__ C,
                             int M, int Ncols, int K) {
    __shared__ float As[16][68];
    __shared__ float Bs[16][64];
    const int bm = blockIdx.y * 64, bn = blockIdx.x * 64;
    const int tid = threadIdx.x;
    const int tx = tid & 15, ty = tid >> 4;
    const int arow = tid >> 2, acol4 = (tid & 3) << 2;
    const int brow = tid >> 4, bcol4 = (tid & 15) << 2;
    float acc[4][4] = {};
    for (int k0 = 0; k0 < K; k0 += 16) {
        float4 av = make_float4(0.f, 0.f, 0.f, 0.f);
        if (bm + arow < M)
            av = *(const float4*)(A + (size_t)(bm + arow) * K + k0 + acol4);
        As[acol4 + 0][arow] = av.x; As[acol4 + 1][arow] = av.y;
        As[acol4 + 2][arow] = av.z; As[acol4 + 3][arow] = av.w;
        float4 bv = make_float4(0.f, 0.f, 0.f, 0.f);
        if (bn + bcol4 < Ncols)
            bv = *(const float4*)(B + (size_t)(k0 + brow) * Ncols + bn + bcol4);
        *(float4*)&Bs[brow][bcol4] = bv;
        __syncthreads();
#pragma unroll
        for (int k = 0; k < 16; k++) {
            float a[4], b[4];
#pragma unroll
            for (int i = 0; i < 4; i++) a[i] = As[k][ty * 4 + i];
#pragma unroll
            for (int j = 0; j < 4; j++) b[j] = Bs[k][tx * 4 + j];
#pragma unroll
            for (int i = 0; i < 4; i++)
#pragma unroll
                for (int j = 0; j < 4; j++) acc[i][j] += a[i] * b[j];
        }
        __syncthreads();
    }
#pragma unroll
    for (int i = 0; i < 4; i++) {
        int r = bm + ty * 4 + i;
        if (r >= M) continue;
#pragma unroll
        for (int j = 0; j < 4; j++) {
            int c = bn + tx * 4 + j;
            if (c >= Ncols) continue;
            float v = acc[i][j];
            if (BIAS) v += bias[c];
            if (ACT == 1) v = fmaxf(v, 0.f);
            if (ACT == 2) v = 1.f / (1.f + expf(-v));
            C[(size_t)r * Ncols + c] = v;
        }
    }
}

// ---------------- build compression windows ---------------------------------
__global__ void build_windows_kernel(const float* __restrict__ k_pos,
                                     const float* __restrict__ v_pos) {
    int idx = blockIdx.x * blockDim.x + threadIdx.x;
    if (idx >= KVH_ * NCB_ * CBS_ * D_) return;
    int d  = idx % D_;
    int t  = (idx / D_) % CBS_;
    int c  = (idx / (D_ * CBS_)) % NCB_;
    int kh = idx / (D_ * CBS_ * NCB_);
    int pos = c * STRIDE_ + t - (CBS_ - STRIDE_);
    float kv = 0.f, vv = 0.f;
    if (pos >= 0) {
        kv = g_qkv[(size_t)pos * QKVW_ + H_ * D_ + kh * D_ + d];
        vv = g_qkv[(size_t)pos * QKVW_ + (H_ + KVH_) * D_ + kh * D_ + d];
    }
    kv += k_pos[(kh * CBS_ + t) * D_ + d];
    vv += v_pos[(kh * CBS_ + t) * D_ + d];
    size_t row = (size_t)kh * NCB_ + c;
    g_kwflat[row * HID_ + t * D_ + d] = kv;
    g_vwflat[row * HID_ + t * D_ + d] = vv;
}

// ---------------- assemble ck / cv (prepend mem token) -----------------------
__global__ void assemble_c_kernel(const float* __restrict__ mem_kv) {
    int idx = blockIdx.x * blockDim.x + threadIdx.x;
    if (idx >= KVH_ * CJ_ * D_) return;
    int d  = idx % D_;
    int j  = (idx / D_) % CJ_;
    int kh = idx / (D_ * CJ_);
    float kvv, vvv;
    if (j < NMEM_) {
        kvv = mem_kv[((0 * KVH_ + kh) * NMEM_ + j) * D_ + d];
        vvv = mem_kv[((1 * KVH_ + kh) * NMEM_ + j) * D_ + d];
    } else {
        kvv = g_ckraw[((size_t)kh * NCB_ + (j - NMEM_)) * D_ + d];
        vvv = g_cvraw[((size_t)kh * NCB_ + (j - NMEM_)) * D_ + d];
    }
    g_ck[idx] = kvv;
    g_cv[idx] = vvv;
}

// ---------------- RoPE -------------------------------------------------------
__global__ void rope_kernel() {
    int idx = blockIdx.x * blockDim.x + threadIdx.x;  // (H+KVH) * N * D/2
    if (idx >= (H_ + KVH_) * N_ * (D_ / 2)) return;
    int m = idx % (D_ / 2);
    int n = (idx / (D_ / 2)) % N_;
    int h = idx / ((D_ / 2) * N_);
    float inv = 1.f / powf(10000.f, (2.f * (float)m) / (float)D_);
    float ang = (float)n * inv;
    float c = cosf(ang), s = sinf(ang);
    const float* src;
    float* dst;
    if (h < H_) {
        src = g_qkv + (size_t)n * QKVW_ + h * D_;
        dst = g_rq + ((size_t)h * N_ + n) * D_;
    } else {
        int kh = h - H_;
        src = g_qkv + (size_t)n * QKVW_ + H_ * D_ + kh * D_;
        dst = g_rk + ((size_t)kh * N_ + n) * D_;
    }
    float a = src[2 * m], b = src[2 * m + 1];
    dst[2 * m]     = a * c - b * s;
    dst[2 * m + 1] = b * c + a * s;
}

// ---------------- compressed attention + importance -------------------------
__global__ void cattn_kernel() {
    int i  = blockIdx.x % N_;
    int kh = blockIdx.x / N_;
    __shared__ float qs[2][D_];
    __shared__ float sims[2][CJ_];
    __shared__ float red[2][2];
    int tid = threadIdx.x;  // 128
    {
        int g = tid / D_, d = tid % D_;
        qs[g][d] = g_qkv[(size_t)i * QKVW_ + (kh * GQ_ + g) * D_ + d];
    }
    __syncthreads();
    for (int j = tid; j < CJ_; j += 128) {
        const float* kr = g_ck + ((size_t)kh * CJ_ + j) * D_;
        float s0 = 0.f, s1 = 0.f;
#pragma unroll
        for (int d = 0; d < D_; d++) { float kv = kr[d]; s0 += qs[0][d] * kv; s1 += qs[1][d] * kv; }
        sims[0][j] = s0 * SCALE_;
        sims[1][j] = s1 * SCALE_;
    }
    __syncthreads();
    // importance (pre-softmax, averaged over GQ and stride pairs)
    for (int fb = tid; fb < NFB_; fb += 128) {
        float v = 0.25f * (sims[0][NMEM_ + 2 * fb] + sims[0][NMEM_ + 2 * fb + 1] +
                           sims[1][NMEM_ + 2 * fb] + sims[1][NMEM_ + 2 * fb + 1]);
        g_imp[((size_t)kh * N_ + i) * NFB_ + fb] = v;
    }
    if (tid < 64) {
        int g = tid / 32, lane = tid % 32;
        float m = -FLT_MAX;
        for (int j = lane; j < CJ_; j += 32) m = fmaxf(m, sims[g][j]);
        for (int o = 16; o; o >>= 1) m = fmaxf(m, __shfl_xor_sync(0xffffffffu, m, o));
        float sm = 0.f;
        for (int j = lane; j < CJ_; j += 32) sm += expf(sims[g][j] - m);
        for (int o = 16; o; o >>= 1) sm += __shfl_xor_sync(0xffffffffu, sm, o);
        if (lane == 0) { red[g][0] = m; red[g][1] = sm; }
    }
    __syncthreads();
    for (int j = tid; j < 2 * CJ_; j += 128) {
        int g = j / CJ_, jj = j % CJ_;
        sims[g][jj] = expf(sims[g][jj] - red[g][0]) / red[g][1];
    }
    __syncthreads();
    {
        int g = tid / D_, d = tid % D_;
        float acc = 0.f;
        for (int j = 0; j < CJ_; j++)
            acc += sims[g][j] * g_cv[((size_t)kh * CJ_ + j) * D_ + d];
        g_cout[(((size_t)(kh * GQ_ + g)) * N_ + i) * D_ + d] = acc;
    }
}

// ---------------- importance softmax + top-k selection ----------------------
__global__ void topk_kernel() {
    int idx = blockIdx.x * blockDim.x + threadIdx.x;  // KVH * N
    if (idx >= KVH_ * N_) return;
    int i = idx % N_;
    const float* row = g_imp + (size_t)idx * NFB_;
    int qb = i / SEL_BLK_;
    float vals[NFB_];
    float m = -1000.f;  // the pad column participates in the max
    for (int fb = 0; fb < NFB_; fb++) {
        float v = (fb == qb) ? -FLT_MAX : row[fb];
        vals[fb] = v;
        m = fmaxf(m, v);
    }
    float sum = expf(-1000.f - m);
    for (int fb = 0; fb < NFB_; fb++) sum += expf(vals[fb] - m);
    float p[NFB_];
    for (int fb = 0; fb < NFB_; fb++) p[fb] = expf(vals[fb] - m) / sum;
    unsigned long long used = 0ull;
    for (int s = 0; s < NSEL_; s++) {
        float best = -1.f; int bi = 0;
        for (int fb = 0; fb < NFB_; fb++) {
            if ((used >> fb) & 1ull) continue;
            if (p[fb] > best) { best = p[fb]; bi = fb; }
        }
        used |= 1ull << bi;
        g_selidx[(size_t)idx * 5 + s] = bi;
        g_selflag[(size_t)idx * 4 + s] = (best > 1e-10f) ? 1 : 0;
    }
    g_selidx[(size_t)idx * 5 + 4] = qb;
}

// ---------------- fine (selected-block) attention ----------------------------
__global__ void fattn_kernel() {
    int i  = blockIdx.x % N_;
    int kh = blockIdx.x / N_;
    __shared__ float qs[2][D_];
    __shared__ float sims[2][5 * SEL_BLK_];
    __shared__ int   sblk[5];
    __shared__ int   sfl[5];
    __shared__ float red[2][2];
    int tid = threadIdx.x;  // 160
    if (tid < 5) {
        sblk[tid] = g_selidx[((size_t)kh * N_ + i) * 5 + tid];
        sfl[tid]  = (tid < 4) ? g_selflag[((size_t)kh * N_ + i) * 4 + tid] : 1;
    }
    if (tid < 128) {
        int g = tid / D_, d = tid % D_;
        qs[g][d] = g_rq[(((size_t)(kh * GQ_ + g)) * N_ + i) * D_ + d];
    }
    __syncthreads();
    {
        int s = tid / SEL_BLK_, t = tid % SEL_BLK_;
        int blk = sblk[s];
        int pos = blk * SEL_BLK_ + t;
        bool valid = (s < 4) ? (sfl[s] != 0) : (t <= (i % SEL_BLK_));
        float s0, s1;
        if (valid) {
            const float* kr = g_rk + ((size_t)kh * N_ + pos) * D_;
            s0 = 0.f; s1 = 0.f;
#pragma unroll
            for (int d = 0; d < D_; d++) { float kv = kr[d]; s0 += qs[0][d] * kv; s1 += qs[1][d] * kv; }
            s0 *= SCALE_; s1 *= SCALE_;
        } else {
            s0 = s1 = -FLT_MAX / 10.f;
        }
        sims[0][tid] = s0;
        sims[1][tid] = s1;
    }
    __syncthreads();
    if (tid < 64) {
        int g = tid / 32, lane = tid % 32;
        float m = -FLT_MAX;
        for (int j = lane; j < 160; j += 32) m = fmaxf(m, sims[g][j]);
        for (int o = 16; o; o >>= 1) m = fmaxf(m, __shfl_xor_sync(0xffffffffu, m, o));
        float sm = 0.f;
        for (int j = lane; j < 160; j += 32) sm += expf(sims[g][j] - m);
        for (int o = 16; o; o >>= 1) sm += __shfl_xor_sync(0xffffffffu, sm, o);
        if (lane == 0) { red[g][0] = m; red[g][1] = sm; }
    }
    __syncthreads();
    for (int j = tid; j < 320; j += 160) {
        int g = j / 160, jj = j % 160;
        sims[g][jj] = expf(sims[g][jj] - red[g][0]) / red[g][1];
    }
    __syncthreads();
    if (tid < 128) {
        int g = tid / D_, d = tid % D_;
        float acc = 0.f;
#pragma unroll
        for (int s = 0; s < 5; s++) {
            int blk = sblk[s];
            for (int t = 0; t < SEL_BLK_; t++) {
                int pos = blk * SEL_BLK_ + t;
                acc += sims[g][s * SEL_BLK_ + t] *
                       g_qkv[(size_t)pos * QKVW_ + (H_ + KVH_) * D_ + kh * D_ + d];
            }
        }
        g_fout[(((size_t)(kh * GQ_ + g)) * N_ + i) * D_ + d] = acc;
    }
}

// ---------------- sliding-window attention -----------------------------------
__global__ void sattn_kernel() {
    int i = blockIdx.x % N_;
    int h = blockIdx.x / N_;
    int kh = h / GQ_;
    __shared__ float qs[D_];
    __shared__ float attn[WS_];
    __shared__ float red[2];
    int tid = threadIdx.x;  // 64
    qs[tid] = g_rq[((size_t)h * N_ + i) * D_ + tid];
    __syncthreads();
    int p = i - (WS_ - 1) + tid;
    float sv = -FLT_MAX;
    if (p >= 0) {
        const float* kr = g_rk + ((size_t)kh * N_ + p) * D_;
        float s = 0.f;
#pragma unroll
        for (int d = 0; d < D_; d++) s += qs[d] * kr[d];
        sv = s * SCALE_;
    }
    attn[tid] = sv;
    __syncthreads();
    if (tid < 32) {
        float a0 = attn[tid], a1 = attn[tid + 32];
        float m = fmaxf(a0, a1);
        for (int o = 16; o; o >>= 1) m = fmaxf(m, __shfl_xor_sync(0xffffffffu, m, o));
        float sm = expf(a0 - m) + expf(a1 - m);
        for (int o = 16; o; o >>= 1) sm += __shfl_xor_sync(0xffffffffu, sm, o);
        if (tid == 0) { red[0] = m; red[1] = sm; }
    }
    __syncthreads();
    float m = red[0], sinv = 1.f / red[1];
    float pr = expf(attn[tid] - m) * sinv;  // expf(-inf)=0 for invalid
    __syncthreads();
    attn[tid] = pr;
    __syncthreads();
    float acc = 0.f;
    int d = tid;
    for (int t = 0; t < WS_; t++) {
        int pp = i - (WS_ - 1) + t;
        if (pp < 0) continue;
        acc += attn[t] * g_qkv[(size_t)pp * QKVW_ + (H_ + KVH_) * D_ + kh * D_ + d];
    }
    g_sout[((size_t)h * N_ + i) * D_ + d] = acc;
}

// ---------------- gated combine ----------------------------------------------
__global__ void combine_kernel() {
    int idx = blockIdx.x * blockDim.x + threadIdx.x;  // N*H*D
    if (idx >= N_ * H_ * D_) return;
    int d = idx % D_;
    int h = (idx / D_) % H_;
    int n = idx / (D_ * H_);
    const float* g = g_gates + ((size_t)n * H_ + h) * 3;
    size_t hnd = ((size_t)h * N_ + n) * D_ + d;
    g_comb[(size_t)n * DIM_ + h * D_ + d] =
        g[0] * g_cout[hnd] + g[1] * g_fout[hnd] + g[2] * g_sout[hnd];
}

// ---------------- launch -----------------------------------------------------
extern "C" void kernel_launch(void* const* d_in, const int* in_sizes, int n_in,
                              void* d_out, int out_size) {
    const float* inp    = (const float*)d_in[0];
    const float* norm_g = (const float*)d_in[1];
    const float* Wqkv   = (const float*)d_in[2];
    const float* mem_kv = (const float*)d_in[3];
    const float* k_pos  = (const float*)d_in[4];
    const float* v_pos  = (const float*)d_in[5];
    const float* kW1    = (const float*)d_in[6];
    const float* kb1    = (const float*)d_in[7];
    const float* kW2    = (const float*)d_in[8];
    const float* kb2    = (const float*)d_in[9];
    const float* vW1    = (const float*)d_in[10];
    const float* vb1    = (const float*)d_in[11];
    const float* vW2    = (const float*)d_in[12];
    const float* vb2    = (const float*)d_in[13];
    const float* combW  = (const float*)d_in[14];
    const float* combB  = (const float*)d_in[15];
    const float* Wout   = (const float*)d_in[16];
    float* out = (float*)d_out;

    float* px;     cudaGetSymbolAddress((void**)&px, g_x);
    float* pqkv;   cudaGetSymbolAddress((void**)&pqkv, g_qkv);
    float* pkw;    cudaGetSymbolAddress((void**)&pkw, g_kwflat);
    float* pvw;    cudaGetSymbolAddress((void**)&pvw, g_vwflat);
    float* ph1;    cudaGetSymbolAddress((void**)&ph1, g_h1);
    float* pckr;   cudaGetSymbolAddress((void**)&pckr, g_ckraw);
    float* pcvr;   cudaGetSymbolAddress((void**)&pcvr, g_cvraw);
    float* pgates; cudaGetSymbolAddress((void**)&pgates, g_gates);
    float* pcomb;  cudaGetSymbolAddress((void**)&pcomb, g_comb);

    // 1. RMSNorm
    rmsnorm_kernel<<<N_, 256>>>(inp, norm_g);
    // 2. qkv = x @ Wqkv   (2048 x 2048 x 1024)
    sgemm_kernel<0, false><<<dim3(QKVW_ / 64, N_ / 64), 256>>>(px, Wqkv, nullptr, pqkv, N_, QKVW_, DIM_);
    // 3. build compression windows
    build_windows_kernel<<<(KVH_ * NCB_ * CBS_ * D_ + 255) / 256, 256>>>(k_pos, v_pos);
    // 4-7. compression MLPs
    sgemm_kernel<1, true><<<dim3(HID_ / 64, (KVH_ * NCB_) / 64), 256>>>(pkw, kW1, kb1, ph1, KVH_ * NCB_, HID_, HID_);
    sgemm_kernel<0, true><<<dim3(1, (KVH_ * NCB_) / 64), 256>>>(ph1, kW2, kb2, pckr, KVH_ * NCB_, D_, HID_);
    sgemm_kernel<1, true><<<dim3(HID_ / 64, (KVH_ * NCB_) / 64), 256>>>(pvw, vW1, vb1, ph1, KVH_ * NCB_, HID_, HID_);
    sgemm_kernel<0, true><<<dim3(1, (KVH_ * NCB_) / 64), 256>>>(ph1, vW2, vb2, pcvr, KVH_ * NCB_, D_, HID_);
    // 8. assemble ck/cv with mem token
    assemble_c_kernel<<<(KVH_ * CJ_ * D_ + 255) / 256, 256>>>(mem_kv);
    // 9. RoPE
    rope_kernel<<<((H_ + KVH_) * N_ * (D_ / 2) + 255) / 256, 256>>>();
    // 10. compressed attention + importance
    cattn_kernel<<<KVH_ * N_, 128>>>();
    // 11. importance softmax + top-k
    topk_kernel<<<(KVH_ * N_ + 255) / 256, 256>>>();
    // 12. fine attention
    fattn_kernel<<<KVH_ * N_, 160>>>();
    // 13. sliding-window attention
    sattn_kernel<<<H_ * N_, 64>>>();
    // 14. gates
    sgemm_kernel<2, true><<<dim3(1, N_ / 64), 256>>>(px, combW, combB, pgates, N_, H_ * 3, DIM_);
    // 15. combine
    combine_kernel<<<(N_ * H_ * D_ + 255) / 256, 256>>>();
    // 16. out = comb @ Wout
    sgemm_kernel<0, false><<<dim3(DIM_ / 64, N_ / 64), 256>>>(pcomb, Wout, nullptr, out, N_, DIM_, DIM_);
}

// round 2
// speedup vs baseline: 2.0292x; 2.0292x over previous
#include <cuda_runtime.h>
#include <math.h>
#include <float.h>

#define N_      2048
#define DIM_    1024
#define H_      16
#define KVH_    8
#define GQ_     2
#define D_      64
#define WS_     64
#define CBS_    32
#define STRIDE_ 16
#define SEL_BLK_ 32
#define NSEL_   4
#define NMEM_   1
#define NCB_    128
#define NFB_    64
#define HID_    2048
#define SCALE_  0.125f
#define QKVW_   2048            /* (H + 2*KVH) * D */
#define CJ_     (NMEM_ + NCB_)  /* 129 */
#define CJP_    144             /* CJ padded to mult of 16 */

// ---------------- scratch (static device allocations) -----------------------
__device__ float g_x[N_ * DIM_];
__device__ float g_qkv[N_ * QKVW_];
__device__ float g_kwflat[KVH_ * NCB_ * HID_];
__device__ float g_vwflat[KVH_ * NCB_ * HID_];
__device__ float g_h1[KVH_ * NCB_ * HID_];
__device__ float g_ckraw[KVH_ * NCB_ * D_];
__device__ float g_cvraw[KVH_ * NCB_ * D_];
__device__ float g_ckT[KVH_ * D_ * CJP_];     // [kh][d][jp]
__device__ float g_cvpad[KVH_ * CJP_ * D_];   // [kh][jp][d], pad rows zero
__device__ float g_qc[H_ * N_ * D_];          // non-rope q, [h][n][d]
__device__ float g_csim[KVH_ * (GQ_ * N_) * CJP_];
__device__ float g_rq[H_ * N_ * D_];
__device__ float g_rk[KVH_ * N_ * D_];
__device__ float g_cout[H_ * N_ * D_];
__device__ float g_fout[H_ * N_ * D_];
__device__ float g_sout[H_ * N_ * D_];
__device__ float g_imp[KVH_ * N_ * NFB_];
__device__ int   g_selidx[KVH_ * N_ * 5];
__device__ int   g_selflag[KVH_ * N_ * 4];
__device__ float g_gates[N_ * H_ * 3];
__device__ float g_comb[N_ * DIM_];
__device__ float g_part[4 * N_ * 64];         // split-K partials (max use)

// ---------------- RMSNorm ---------------------------------------------------
__global__ void rmsnorm_kernel(const float* __restrict__ inp,
                               const float* __restrict__ gamma) {
    int row = blockIdx.x;
    const float* r = inp + (size_t)row * DIM_;
    float s = 0.f;
    for (int j = threadIdx.x; j < DIM_; j += blockDim.x) { float v = r[j]; s += v * v; }
    __shared__ float sh[32];
    for (int o = 16; o; o >>= 1) s += __shfl_down_sync(0xffffffffu, s, o);
    if ((threadIdx.x & 31) == 0) sh[threadIdx.x >> 5] = s;
    __syncthreads();
    if (threadIdx.x < 32) {
        s = (threadIdx.x < (blockDim.x >> 5)) ? sh[threadIdx.x] : 0.f;
        for (int o = 16; o; o >>= 1) s += __shfl_down_sync(0xffffffffu, s, o);
        if (threadIdx.x == 0) sh[0] = rsqrtf(s / (float)DIM_ + 1.1920929e-07f);
    }
    __syncthreads();
    float rs = sh[0];
    for (int j = threadIdx.x; j < DIM_; j += blockDim.x)
        g_x[(size_t)row * DIM_ + j] = r[j] * rs * gamma[j];
}

// ---------------- SGEMM (generalized: lda/ldb/ldc + z-batch strides) --------
// A (M,K) lda, B (K,N) ldb, row-major. 64x64 tile, BK=16, 256 thr, 4x4/thr.
template <int ACT, bool BIAS>
__global__ void sgemm_kernel(const float* __restrict__ A, int lda, long sA,
                             const float* __restrict__ B, int ldb, long sB,
                             const float* __restrict__ bias,
                             float* __restrict__ C, int ldc, long sC,
                             int M, int Ncols, int K) {
    __shared__ float As[16][68];
    __shared__ float Bs[16][64];
    A += (size_t)blockIdx.z * sA;
    B += (size_t)blockIdx.z * sB;
    C += (size_t)blockIdx.z * sC;
    const int bm = blockIdx.y * 64, bn = blockIdx.x * 64;
    const int tid = threadIdx.x;
    const int tx = tid & 15, ty = tid >> 4;
    const int arow = tid >> 2, acol4 = (tid & 3) << 2;
    const int brow = tid >> 4, bcol4 = (tid & 15) << 2;
    float acc[4][4] = {};
    for (int k0 = 0; k0 < K; k0 += 16) {
        float4 av = make_float4(0.f, 0.f, 0.f, 0.f);
        if (bm + arow < M)
            av = *(const float4*)(A + (size_t)(bm + arow) * lda + k0 + acol4);
        As[acol4 + 0][arow] = av.x; As[acol4 + 1][arow] = av.y;
        As[acol4 + 2][arow] = av.z; As[acol4 + 3][arow] = av.w;
        float4 bv = make_float4(0.f, 0.f, 0.f, 0.f);
        if (bn + bcol4 < Ncols)
            bv = *(const float4*)(B + (size_t)(k0 + brow) * ldb + bn + bcol4);
        *(float4*)&Bs[brow][bcol4] = bv;
        __syncthreads();
#pragma unroll
        for (int k = 0; k < 16; k++) {
            float a[4], b[4];
#pragma unroll
            for (int i = 0; i < 4; i++) a[i] = As[k][ty * 4 + i];
#pragma unroll
            for (int j = 0; j < 4; j++) b[j] = Bs[k][tx * 4 + j];
#pragma unroll
            for (int i = 0; i < 4; i++)
#pragma unroll
                for (int j = 0; j < 4; j++) acc[i][j] += a[i] * b[j];
        }
        __syncthreads();
    }
#pragma unroll
    for (int i = 0; i < 4; i++) {
        int r = bm + ty * 4 + i;
        if (r >= M) continue;
#pragma unroll
        for (int j = 0; j < 4; j++) {
            int c = bn + tx * 4 + j;
            if (c >= Ncols) continue;
            float v = acc[i][j];
            if (BIAS) v += bias[c];
            if (ACT == 1) v = fmaxf(v, 0.f);
            C[(size_t)r * ldc + c] = v;
        }
    }
}

// ---------------- split-K reduce (Z=4) ---------------------------------------
template <int ACT>
__global__ void reduce4_kernel(const float* __restrict__ part,
                               const float* __restrict__ bias,
                               float* __restrict__ out, int total, int ncols) {
    int idx = blockIdx.x * blockDim.x + threadIdx.x;
    if (idx >= total) return;
    float v = part[idx] + part[idx + total] + part[idx + 2 * total] +
              part[idx + 3 * total] + bias[idx % ncols];
    if (ACT == 2) v = 1.f / (1.f + expf(-v));
    out[idx] = v;
}

// ---------------- build compression windows ---------------------------------
__global__ void build_windows_kernel(const float* __restrict__ k_pos,
                                     const float* __restrict__ v_pos) {
    int idx = blockIdx.x * blockDim.x + threadIdx.x;
    if (idx >= KVH_ * NCB_ * CBS_ * D_) return;
    int d  = idx % D_;
    int t  = (idx / D_) % CBS_;
    int c  = (idx / (D_ * CBS_)) % NCB_;
    int kh = idx / (D_ * CBS_ * NCB_);
    int pos = c * STRIDE_ + t - (CBS_ - STRIDE_);
    float kv = 0.f, vv = 0.f;
    if (pos >= 0) {
        kv = g_qkv[(size_t)pos * QKVW_ + H_ * D_ + kh * D_ + d];
        vv = g_qkv[(size_t)pos * QKVW_ + (H_ + KVH_) * D_ + kh * D_ + d];
    }
    kv += k_pos[(kh * CBS_ + t) * D_ + d];
    vv += v_pos[(kh * CBS_ + t) * D_ + d];
    size_t row = (size_t)kh * NCB_ + c;
    g_kwflat[row * HID_ + t * D_ + d] = kv;
    g_vwflat[row * HID_ + t * D_ + d] = vv;
}

// ---------------- assemble ckT / cvpad ---------------------------------------
__global__ void assemble_c_kernel(const float* __restrict__ mem_kv) {
    int idx = blockIdx.x * blockDim.x + threadIdx.x;
    if (idx >= KVH_ * CJP_ * D_) return;
    int d  = idx % D_;
    int j  = (idx / D_) % CJP_;
    int kh = idx / (D_ * CJP_);
    float kvv = 0.f, vvv = 0.f;
    if (j < NMEM_) {
        kvv = mem_kv[((0 * KVH_ + kh) * NMEM_ + j) * D_ + d];
        vvv = mem_kv[((1 * KVH_ + kh) * NMEM_ + j) * D_ + d];
    } else if (j < CJ_) {
        kvv = g_ckraw[((size_t)kh * NCB_ + (j - NMEM_)) * D_ + d];
        vvv = g_cvraw[((size_t)kh * NCB_ + (j - NMEM_)) * D_ + d];
    }
    g_ckT[((size_t)kh * D_ + d) * CJP_ + j] = kvv;
    g_cvpad[((size_t)kh * CJP_ + j) * D_ + d] = vvv;
}

// ---------------- RoPE (+ extract non-rope q) --------------------------------
__global__ void rope_kernel() {
    int idx = blockIdx.x * blockDim.x + threadIdx.x;
    if (idx >= (H_ + KVH_) * N_ * (D_ / 2)) return;
    int m = idx % (D_ / 2);
    int n = (idx / (D_ / 2)) % N_;
    int h = idx / ((D_ / 2) * N_);
    float inv = 1.f / powf(10000.f, (2.f * (float)m) / (float)D_);
    float ang = (float)n * inv;
    float c = cosf(ang), s = sinf(ang);
    const float* src;
    float* dst;
    if (h < H_) {
        src = g_qkv + (size_t)n * QKVW_ + h * D_;
        dst = g_rq + ((size_t)h * N_ + n) * D_;
    } else {
        int kh = h - H_;
        src = g_qkv + (size_t)n * QKVW_ + H_ * D_ + kh * D_;
        dst = g_rk + ((size_t)kh * N_ + n) * D_;
    }
    float a = src[2 * m], b = src[2 * m + 1];
    dst[2 * m]     = a * c - b * s;
    dst[2 * m + 1] = b * c + a * s;
    if (h < H_) {
        float* qd = g_qc + ((size_t)h * N_ + n) * D_;
        qd[2 * m] = a; qd[2 * m + 1] = b;
    }
}

// ---------------- importance (pre-softmax csim) ------------------------------
__global__ void importance_kernel() {
    int idx = blockIdx.x * blockDim.x + threadIdx.x;  // KVH*N*NFB
    if (idx >= KVH_ * N_ * NFB_) return;
    int fb = idx % NFB_;
    int i  = (idx / NFB_) % N_;
    int kh = idx / (NFB_ * N_);
    const float* base = g_csim + (size_t)kh * (GQ_ * N_) * CJP_;
    int c = NMEM_ + 2 * fb;
    float v = base[(size_t)i * CJP_ + c] + base[(size_t)i * CJP_ + c + 1] +
              base[(size_t)(N_ + i) * CJP_ + c] + base[(size_t)(N_ + i) * CJP_ + c + 1];
    g_imp[((size_t)kh * N_ + i) * NFB_ + fb] = 0.25f * SCALE_ * v;
}

// ---------------- compressed softmax (in-place, warp per row) ----------------
__global__ void csoftmax_kernel() {
    int row  = blockIdx.x * 8 + (threadIdx.x >> 5);  // 0..KVH*GQ*N-1
    int lane = threadIdx.x & 31;
    float* p = g_csim + (size_t)row * CJP_;
    float v0 = p[lane] * SCALE_, v1 = p[lane + 32] * SCALE_;
    float v2 = p[lane + 64] * SCALE_, v3 = p[lane + 96] * SCALE_;
    float v4 = (lane == 0) ? p[128] * SCALE_ : -FLT_MAX;
    float m = fmaxf(fmaxf(fmaxf(v0, v1), fmaxf(v2, v3)), v4);
    for (int o = 16; o; o >>= 1) m = fmaxf(m, __shfl_xor_sync(0xffffffffu, m, o));
    float e0 = expf(v0 - m), e1 = expf(v1 - m), e2 = expf(v2 - m), e3 = expf(v3 - m);
    float e4 = (lane == 0) ? expf(v4 - m) : 0.f;
    float s = e0 + e1 + e2 + e3 + e4;
    for (int o = 16; o; o >>= 1) s += __shfl_xor_sync(0xffffffffu, s, o);
    float inv = 1.f / s;
    p[lane] = e0 * inv; p[lane + 32] = e1 * inv;
    p[lane + 64] = e2 * inv; p[lane + 96] = e3 * inv;
    if (lane == 0) p[128] = e4 * inv;
    if (lane >= 1 && lane < 16) p[128 + lane] = 0.f;  // zero pad cols
}

// ---------------- top-k (warp per row) ----------------------------------------
__global__ void topk_kernel() {
    int row  = blockIdx.x * 8 + (threadIdx.x >> 5);  // KVH*N rows
    int lane = threadIdx.x & 31;
    int i = row & (N_ - 1);
    int qb = i >> 5;
    const float* ip = g_imp + (size_t)row * NFB_;
    float v0 = (lane == qb)      ? -FLT_MAX : ip[lane];
    float v1 = (lane + 32 == qb) ? -FLT_MAX : ip[lane + 32];
    float m = fmaxf(fmaxf(v0, v1), -1000.f);
    for (int o = 16; o; o >>= 1) m = fmaxf(m, __shfl_xor_sync(0xffffffffu, m, o));
    float s = expf(v0 - m) + expf(v1 - m);
    for (int o = 16; o; o >>= 1) s += __shfl_xor_sync(0xffffffffu, s, o);
    s += expf(-1000.f - m);
    float inv = 1.f / s;
    float p0 = expf(v0 - m) * inv, p1 = expf(v1 - m) * inv;
#pragma unroll
    for (int sel = 0; sel < NSEL_; sel++) {
        float bv; int bi;
        if (p0 >= p1) { bv = p0; bi = lane; } else { bv = p1; bi = lane + 32; }
        for (int o = 16; o; o >>= 1) {
            float ov = __shfl_xor_sync(0xffffffffu, bv, o);
            int   oi = __shfl_xor_sync(0xffffffffu, bi, o);
            if (ov > bv || (ov == bv && oi < bi)) { bv = ov; bi = oi; }
        }
        if (lane == 0) {
            g_selidx[(size_t)row * 5 + sel] = bi;
            g_selflag[(size_t)row * 4 + sel] = (bv > 1e-10f) ? 1 : 0;
        }
        if (bi == lane) p0 = -1.f;
        if (bi == lane + 32) p1 = -1.f;
    }
    if (lane == 0) g_selidx[(size_t)row * 5 + 4] = qb;
}

// ---------------- fine attention (warp-per-keygroup QK) ----------------------
__global__ void fattn_kernel() {
    int i  = blockIdx.x & (N_ - 1);
    int kh = blockIdx.x >> 11;
    __shared__ float qs[2][D_];
    __shared__ float sims[2][5 * SEL_BLK_];
    __shared__ int   sblk[5];
    __shared__ int   sfl[5];
    __shared__ float red[2][2];
    int tid = threadIdx.x;  // 160 = 5 warps
    int w = tid >> 5, lane = tid & 31;
    if (tid < 5) {
        sblk[tid] = g_selidx[((size_t)kh * N_ + i) * 5 + tid];
        sfl[tid]  = (tid < 4) ? g_selflag[((size_t)kh * N_ + i) * 4 + tid] : 1;
    }
    if (tid < 128) {
        int g = tid >> 6, d = tid & 63;
        qs[g][d] = g_rq[(((size_t)(kh * GQ_ + g)) * N_ + i) * D_ + d];
    }
    __syncthreads();
    {
        float q0a = qs[0][lane], q0b = qs[0][lane + 32];
        float q1a = qs[1][lane], q1b = qs[1][lane + 32];
        int blk = sblk[w];
        bool grpvalid = (w < 4) ? (sfl[w] != 0) : true;
        int lim = (w == 4) ? (i & 31) : 31;
        const float* kbase = g_rk + ((size_t)kh * N_ + blk * SEL_BLK_) * D_;
        for (int kk = 0; kk < SEL_BLK_; kk++) {
            float s0 = -FLT_MAX / 10.f, s1 = -FLT_MAX / 10.f;
            if (grpvalid && kk <= lim) {
                float ka = kbase[kk * D_ + lane], kb = kbase[kk * D_ + lane + 32];
                float p0 = q0a * ka + q0b * kb;
                float p1 = q1a * ka + q1b * kb;
                for (int o = 16; o; o >>= 1) {
                    p0 += __shfl_xor_sync(0xffffffffu, p0, o);
                    p1 += __shfl_xor_sync(0xffffffffu, p1, o);
                }
                s0 = p0 * SCALE_; s1 = p1 * SCALE_;
            }
            if (lane == 0) { sims[0][w * 32 + kk] = s0; sims[1][w * 32 + kk] = s1; }
        }
    }
    __syncthreads();
    if (tid < 64) {
        int g = tid >> 5, l = tid & 31;
        float m = -FLT_MAX;
        for (int j = l; j < 160; j += 32) m = fmaxf(m, sims[g][j]);
        for (int o = 16; o; o >>= 1) m = fmaxf(m, __shfl_xor_sync(0xffffffffu, m, o));
        float sm = 0.f;
        for (int j = l; j < 160; j += 32) sm += expf(sims[g][j] - m);
        for (int o = 16; o; o >>= 1) sm += __shfl_xor_sync(0xffffffffu, sm, o);
        if (l == 0) { red[g][0] = m; red[g][1] = sm; }
    }
    __syncthreads();
    for (int j = tid; j < 320; j += 160) {
        int g = j / 160, jj = j % 160;
        sims[g][jj] = expf(sims[g][jj] - red[g][0]) / red[g][1];
    }
    __syncthreads();
    if (tid < 128) {
        int g = tid >> 6, d = tid & 63;
        const float* vbase = g_qkv + (size_t)(H_ + KVH_) * D_ + kh * D_ + d;
        float acc = 0.f;
#pragma unroll
        for (int s = 0; s < 5; s++) {
            int pb = sblk[s] * SEL_BLK_;
#pragma unroll 8
            for (int t = 0; t < SEL_BLK_; t++)
                acc += sims[g][s * 32 + t] * vbase[(size_t)(pb + t) * QKVW_];
        }
        g_fout[(((size_t)(kh * GQ_ + g)) * N_ + i) * D_ + d] = acc;
    }
}

// ---------------- sliding-window attention (tiled, smem) ---------------------
// grid (N/64, H), 256 threads, dynamic smem: K[128*65] + Q[64*65] + P[64*128]
__global__ void sattn_kernel() {
    extern __shared__ float sm[];
    float* Ks = sm;                        // 128 x 65
    float* Qs = sm + 128 * 65;             // 64 x 65
    float* Ps = Qs + 64 * 65;              // 64 x 128
    int tIdx = blockIdx.x, h = blockIdx.y, kh = h >> 1;
    int i0 = tIdx * 64;
    int tid = threadIdx.x, w = tid >> 5, lane = tid & 31;
    for (int idx = tid; idx < 64 * 64; idx += 256) {
        int r = idx >> 6, d = idx & 63;
        Qs[r * 65 + d] = g_rq[((size_t)h * N_ + i0 + r) * D_ + d];
    }
    for (int idx = tid; idx < 128 * 64; idx += 256) {
        int j = idx >> 6, d = idx & 63;
        int p = i0 - 64 + j;
        Ks[j * 65 + d] = (p >= 0) ? g_rk[((size_t)kh * N_ + p) * D_ + d] : 0.f;
    }
    __syncthreads();
    // scores + per-row softmax (warp w owns rows w*8 .. w*8+7; lanes over j)
#pragma unroll
    for (int rr = 0; rr < 8; rr++) {
        int r = w * 8 + rr;
        int j0 = lane, j1 = lane + 32, j2 = lane + 64, j3 = lane + 96;
        float a0 = 0.f, a1 = 0.f, a2 = 0.f, a3 = 0.f;
        for (int d = 0; d < 64; d++) {
            float q = Qs[r * 65 + d];
            a0 += q * Ks[j0 * 65 + d]; a1 += q * Ks[j1 * 65 + d];
            a2 += q * Ks[j2 * 65 + d]; a3 += q * Ks[j3 * 65 + d];
        }
        float s0, s1, s2, s3;
        {
            bool ok;
            ok = (j0 >= r + 1) && (j0 <= r + 64) && (i0 - 64 + j0 >= 0);
            s0 = ok ? a0 * SCALE_ : -FLT_MAX;
            ok = (j1 >= r + 1) && (j1 <= r + 64) && (i0 - 64 + j1 >= 0);
            s1 = ok ? a1 * SCALE_ : -FLT_MAX;
            ok = (j2 >= r + 1) && (j2 <= r + 64) && (i0 - 64 + j2 >= 0);
            s2 = ok ? a2 * SCALE_ : -FLT_MAX;
            ok = (j3 >= r + 1) && (j3 <= r + 64) && (i0 - 64 + j3 >= 0);
            s3 = ok ? a3 * SCALE_ : -FLT_MAX;
        }
        float m = fmaxf(fmaxf(s0, s1), fmaxf(s2, s3));
        for (int o = 16; o; o >>= 1) m = fmaxf(m, __shfl_xor_sync(0xffffffffu, m, o));
        float e0 = expf(s0 - m), e1 = expf(s1 - m), e2 = expf(s2 - m), e3 = expf(s3 - m);
        float su = e0 + e1 + e2 + e3;
        for (int o = 16; o; o >>= 1) su += __shfl_xor_sync(0xffffffffu, su, o);
        float inv = 1.f / su;
        Ps[r * 128 + j0] = e0 * inv; Ps[r * 128 + j1] = e1 * inv;
        Ps[r * 128 + j2] = e2 * inv; Ps[r * 128 + j3] = e3 * inv;
    }
    __syncthreads();
    // load V into K buffer
    for (int idx = tid; idx < 128 * 64; idx += 256) {
        int j = idx >> 6, d = idx & 63;
        int p = i0 - 64 + j;
        Ks[j * 65 + d] = (p >= 0)
            ? g_qkv[(size_t)p * QKVW_ + (H_ + KVH_) * D_ + kh * D_ + d] : 0.f;
    }
    __syncthreads();
#pragma unroll
    for (int rr = 0; rr < 8; rr++) {
        int r = w * 8 + rr;
        float a0 = 0.f, a1 = 0.f;
        for (int j = 0; j < 128; j++) {
            float p = Ps[r * 128 + j];
            a0 += p * Ks[j * 65 + lane];
            a1 += p * Ks[j * 65 + lane + 32];
        }
        size_t ob = ((size_t)h * N_ + i0 + r) * D_;
        g_sout[ob + lane] = a0;
        g_sout[ob + lane + 32] = a1;
    }
}

// ---------------- gated combine ----------------------------------------------
__global__ void combine_kernel() {
    int idx = blockIdx.x * blockDim.x + threadIdx.x;  // N*H*D
    if (idx >= N_ * H_ * D_) return;
    int d = idx % D_;
    int h = (idx / D_) % H_;
    int n = idx / (D_ * H_);
    const float* g = g_gates + ((size_t)n * H_ + h) * 3;
    size_t hnd = ((size_t)h * N_ + n) * D_ + d;
    g_comb[(size_t)n * DIM_ + h * D_ + d] =
        g[0] * g_cout[hnd] + g[1] * g_fout[hnd] + g[2] * g_sout[hnd];
}

// ---------------- launch -----------------------------------------------------
extern "C" void kernel_launch(void* const* d_in, const int* in_sizes, int n_in,
                              void* d_out, int out_size) {
    const float* inp    = (const float*)d_in[0];
    const float* norm_g = (const float*)d_in[1];
    const float* Wqkv   = (const float*)d_in[2];
    const float* mem_kv = (const float*)d_in[3];
    const float* k_pos  = (const float*)d_in[4];
    const float* v_pos  = (const float*)d_in[5];
    const float* kW1    = (const float*)d_in[6];
    const float* kb1    = (const float*)d_in[7];
    const float* kW2    = (const float*)d_in[8];
    const float* kb2    = (const float*)d_in[9];
    const float* vW1    = (const float*)d_in[10];
    const float* vb1    = (const float*)d_in[11];
    const float* vW2    = (const float*)d_in[12];
    const float* vb2    = (const float*)d_in[13];
    const float* combW  = (const float*)d_in[14];
    const float* combB  = (const float*)d_in[15];
    const float* Wout   = (const float*)d_in[16];
    float* out = (float*)d_out;

    float* px;     cudaGetSymbolAddress((void**)&px, g_x);
    float* pqkv;   cudaGetSymbolAddress((void**)&pqkv, g_qkv);
    float* pkw;    cudaGetSymbolAddress((void**)&pkw, g_kwflat);
    float* pvw;    cudaGetSymbolAddress((void**)&pvw, g_vwflat);
    float* ph1;    cudaGetSymbolAddress((void**)&ph1, g_h1);
    float* pckr;   cudaGetSymbolAddress((void**)&pckr, g_ckraw);
    float* pcvr;   cudaGetSymbolAddress((void**)&pcvr, g_cvraw);
    float* pckT;   cudaGetSymbolAddress((void**)&pckT, g_ckT);
    float* pcvp;   cudaGetSymbolAddress((void**)&pcvp, g_cvpad);
    float* pqc;    cudaGetSymbolAddress((void**)&pqc, g_qc);
    float* pcsim;  cudaGetSymbolAddress((void**)&pcsim, g_csim);
    float* pcout;  cudaGetSymbolAddress((void**)&pcout, g_cout);
    float* ppart;  cudaGetSymbolAddress((void**)&ppart, g_part);
    float* pgates; cudaGetSymbolAddress((void**)&pgates, g_gates);
    float* pcomb;  cudaGetSymbolAddress((void**)&pcomb, g_comb);

    static int smem_set = 0;
    const int SATTN_SMEM = (128 * 65 + 64 * 65 + 64 * 128) * 4;
    if (!smem_set) {
        cudaFuncSetAttribute(sattn_kernel, cudaFuncAttributeMaxDynamicSharedMemorySize, SATTN_SMEM);
        smem_set = 1;
    }

    // 1. RMSNorm
    rmsnorm_kernel<<<N_, 256>>>(inp, norm_g);
    // 2. qkv = x @ Wqkv
    sgemm_kernel<0, false><<<dim3(32, 32, 1), 256>>>(px, DIM_, 0, Wqkv, QKVW_, 0, nullptr,
                                                     pqkv, QKVW_, 0, N_, QKVW_, DIM_);
    // 3. windows + rope/qc
    build_windows_kernel<<<(KVH_ * NCB_ * CBS_ * D_ + 255) / 256, 256>>>(k_pos, v_pos);
    rope_kernel<<<((H_ + KVH_) * N_ * (D_ / 2) + 255) / 256, 256>>>();
    // 4. compression MLPs (W2 via split-K x4)
    sgemm_kernel<1, true><<<dim3(32, 16, 1), 256>>>(pkw, HID_, 0, kW1, HID_, 0, kb1,
                                                    ph1, HID_, 0, KVH_ * NCB_, HID_, HID_);
    sgemm_kernel<0, false><<<dim3(1, 16, 4), 256>>>(ph1, HID_, 512, kW2, D_, (long)512 * D_,
                                                    nullptr, ppart, D_, (long)1024 * D_,
                                                    KVH_ * NCB_, D_, 512);
    reduce4_kernel<0><<<(1024 * D_ + 255) / 256, 256>>>(ppart, kb2, pckr, 1024 * D_, D_);
    sgemm_kernel<1, true><<<dim3(32, 16, 1), 256>>>(pvw, HID_, 0, vW1, HID_, 0, vb1,
                                                    ph1, HID_, 0, KVH_ * NCB_, HID_, HID_);
    sgemm_kernel<0, false><<<dim3(1, 16, 4), 256>>>(ph1, HID_, 512, vW2, D_, (long)512 * D_,
                                                    nullptr, ppart, D_, (long)1024 * D_,
                                                    KVH_ * NCB_, D_, 512);
    reduce4_kernel<0><<<(1024 * D_ + 255) / 256, 256>>>(ppart, vb2, pcvr, 1024 * D_, D_);
    // 5. assemble ckT / cvpad
    assemble_c_kernel<<<(KVH_ * CJP_ * D_ + 255) / 256, 256>>>(mem_kv);
    // 6. compressed attention as batched GEMMs + softmax
    sgemm_kernel<0, false><<<dim3(3, 64, KVH_), 256>>>(
        pqc, D_, (long)(GQ_ * N_) * D_, pckT, CJP_, (long)D_ * CJP_, nullptr,
        pcsim, CJP_, (long)(GQ_ * N_) * CJP_, GQ_ * N_, CJ_, D_);
    importance_kernel<<<(KVH_ * N_ * NFB_ + 255) / 256, 256>>>();
    csoftmax_kernel<<<KVH_ * GQ_ * N_ / 8, 256>>>();
    sgemm_kernel<0, false><<<dim3(1, 64, KVH_), 256>>>(
        pcsim, CJP_, (long)(GQ_ * N_) * CJP_, pcvp, D_, (long)CJP_ * D_, nullptr,
        pcout, D_, (long)(GQ_ * N_) * D_, GQ_ * N_, D_, CJP_);
    // 7. top-k + fine attention
    topk_kernel<<<KVH_ * N_ / 8, 256>>>();
    fattn_kernel<<<KVH_ * N_, 160>>>();
    // 8. sliding-window attention (tiled)
    sattn_kernel<<<dim3(N_ / 64, H_), 256, SATTN_SMEM>>>();
    // 9. gates (split-K x4) + combine + output
    sgemm_kernel<0, false><<<dim3(1, 32, 4), 256>>>(px, DIM_, 256, combW, 48, (long)256 * 48,
                                                    nullptr, ppart, 48, (long)N_ * 48,
                                                    N_, 48, 256);
    reduce4_kernel<2><<<(N_ * 48 + 255) / 256, 256>>>(ppart, combB, pgates, N_ * 48, 48);
    combine_kernel<<<(N_ * H_ * D_ + 255) / 256, 256>>>();
    sgemm_kernel<0, false><<<dim3(16, 32, 1), 256>>>(pcomb, DIM_, 0, Wout, DIM_, 0, nullptr,
                                                     out, DIM_, 0, N_, DIM_, DIM_);
}